// round 1
// baseline (speedup 1.0000x reference)
#include <cuda_runtime.h>
#include <math.h>

#define TOK  4096
#define BB   2
#define SS   2048
#define D1   512
#define D2   1024
#define NH   8
#define HD   128
#define NBG  4
#define BLKG 256
#define KSZ  4
#define EPSF 1e-5f

// ---------------- scratch (device globals; no allocation allowed) -------------
static __device__ float g_xn[TOK*D1];
static __device__ float g_a [TOK*D2];
static __device__ float g_bg[TOK*D2];
static __device__ float g_qk[TOK*D2];
static __device__ float g_q [TOK*D2];
static __device__ float g_k [TOK*D2];
static __device__ float g_v [TOK*D2];
static __device__ float g_qh[TOK*D2];
static __device__ float g_kh[TOK*D2];
static __device__ float g_vh[TOK*D2];
static __device__ float g_Ho[TOK*D2];
static __device__ float g_h2[TOK*D2];
static __device__ float g_wc[KSZ*D2*D2];
static __device__ float g_it[BB*NH*SS];
static __device__ float g_ft[BB*NH*SS];
static __device__ float g_cs[BB*NH*SS];
static __device__ float g_mm[BB*NH*SS];
static __device__ float g_Mx[BB*NH*SS];

// ---------------- layernorm over last dim (512), warp per token ---------------
__global__ void ln_kernel(const float* __restrict__ x,
                          const float* __restrict__ w,
                          const float* __restrict__ b) {
    int t = blockIdx.x * 8 + (threadIdx.x >> 5);
    int lane = threadIdx.x & 31;
    const float* xr = x + (size_t)t * D1;
    float v[16]; float s = 0.f;
#pragma unroll
    for (int i = 0; i < 16; i++) { v[i] = xr[lane + 32*i]; s += v[i]; }
#pragma unroll
    for (int o = 16; o; o >>= 1) s += __shfl_xor_sync(0xffffffffu, s, o);
    float mu = s * (1.f / D1);
    float q = 0.f;
#pragma unroll
    for (int i = 0; i < 16; i++) { float d = v[i] - mu; q += d * d; }
#pragma unroll
    for (int o = 16; o; o >>= 1) q += __shfl_xor_sync(0xffffffffu, q, o);
    float rstd = rsqrtf(q * (1.f / D1) + EPSF);
#pragma unroll
    for (int i = 0; i < 16; i++) {
        int c = lane + 32*i;
        g_xn[(size_t)t*D1 + c] = (v[i] - mu) * rstd * w[c] + b[c];
    }
}

// ---------------- generic tiled SGEMM: C = act(A@B + bias) (+res) -------------
// A row-major [M,K] lda, B row-major [K,N] ldb. 64x64 tile, BK=16, 256 threads.
// ACT: 0 = none, 1 = silu, 2 = add residual
template<int ACT>
__global__ void __launch_bounds__(256) sgemm_kernel(
    const float* __restrict__ A, int lda,
    const float* __restrict__ B, int ldb,
    const float* __restrict__ bias,
    const float* __restrict__ res, int ldr,
    float* __restrict__ C, int ldc,
    int M, int N, int K)
{
    __shared__ float As[16][68];
    __shared__ float Bs[16][68];
    int m0 = blockIdx.y * 64, n0 = blockIdx.x * 64;
    int tid = threadIdx.x;
    int ty = tid >> 4, tx = tid & 15;
    int ar = tid >> 2, ak = (tid & 3) * 4;
    int bk = tid >> 4, bn = (tid & 15) * 4;
    const float* Ap = A + (size_t)(m0 + ar) * lda + ak;
    const float* Bp = B + (size_t)bk * ldb + n0 + bn;
    float acc[4][4] = {};
    for (int k0 = 0; k0 < K; k0 += 16) {
        float4 av = *(const float4*)(Ap + k0);
        As[ak+0][ar] = av.x; As[ak+1][ar] = av.y;
        As[ak+2][ar] = av.z; As[ak+3][ar] = av.w;
        float4 bv = *(const float4*)(Bp + (size_t)k0 * ldb);
        *(float4*)&Bs[bk][bn] = bv;
        __syncthreads();
#pragma unroll
        for (int kk = 0; kk < 16; kk++) {
            float a[4], b[4];
#pragma unroll
            for (int r = 0; r < 4; r++) a[r] = As[kk][ty*4 + r];
#pragma unroll
            for (int c = 0; c < 4; c++) b[c] = Bs[kk][tx*4 + c];
#pragma unroll
            for (int r = 0; r < 4; r++)
#pragma unroll
                for (int c = 0; c < 4; c++)
                    acc[r][c] = fmaf(a[r], b[c], acc[r][c]);
        }
        __syncthreads();
    }
#pragma unroll
    for (int r = 0; r < 4; r++) {
        int m = m0 + ty*4 + r;
#pragma unroll
        for (int c = 0; c < 4; c++) {
            int n = n0 + tx*4 + c;
            float v = acc[r][c];
            if (bias) v += bias[n];
            if (ACT == 1) v = v / (1.f + expf(-v));
            if (ACT == 2) v += res[(size_t)m * ldr + n];
            C[(size_t)m * ldc + n] = v;
        }
    }
}

// ---------------- conv_w [O,I,K] -> g_wc [K][I][O] (coalesced read) ------------
__global__ void conv_tr(const float* __restrict__ cw) {
    int idx = blockIdx.x * 256 + threadIdx.x;
    if (idx >= KSZ * D2 * D2) return;
    int o   = idx >> 12;
    int rem = idx & 4095;
    int i   = rem >> 2;
    int kk  = rem & 3;
    g_wc[((size_t)kk * D2 + i) * D2 + o] = cw[idx];
}

// ---------------- causal conv1d as 4 shifted GEMMs, + bias + silu --------------
__global__ void __launch_bounds__(256) conv_gemm(const float* __restrict__ cb) {
    __shared__ float As[16][68];
    __shared__ float Bs[16][68];
    int m0 = blockIdx.y * 64, n0 = blockIdx.x * 64;
    int tid = threadIdx.x;
    int ty = tid >> 4, tx = tid & 15;
    int ar = tid >> 2, ak = (tid & 3) * 4;
    int bk = tid >> 4, bn = (tid & 15) * 4;
    int m = m0 + ar;
    int sl = m & (SS - 1);
    float acc[4][4] = {};
    for (int kc = 0; kc < KSZ; kc++) {
        const float* Bk = g_wc + (size_t)kc * D2 * D2;
        int shift = kc - (KSZ - 1);
        bool valid = (sl + shift) >= 0;
        const float* Arow = g_a + (size_t)(m + shift) * D2;
        for (int k0 = 0; k0 < D2; k0 += 16) {
            float4 av = valid ? *(const float4*)(Arow + k0 + ak)
                              : make_float4(0.f, 0.f, 0.f, 0.f);
            As[ak+0][ar] = av.x; As[ak+1][ar] = av.y;
            As[ak+2][ar] = av.z; As[ak+3][ar] = av.w;
            float4 bv = *(const float4*)(Bk + (size_t)(k0 + bk) * D2 + n0 + bn);
            *(float4*)&Bs[bk][bn] = bv;
            __syncthreads();
#pragma unroll
            for (int kk = 0; kk < 16; kk++) {
                float a[4], b[4];
#pragma unroll
                for (int r = 0; r < 4; r++) a[r] = As[kk][ty*4 + r];
#pragma unroll
                for (int c = 0; c < 4; c++) b[c] = Bs[kk][tx*4 + c];
#pragma unroll
                for (int r = 0; r < 4; r++)
#pragma unroll
                    for (int c = 0; c < 4; c++)
                        acc[r][c] = fmaf(a[r], b[c], acc[r][c]);
            }
            __syncthreads();
        }
    }
#pragma unroll
    for (int r = 0; r < 4; r++) {
        int mm = m0 + ty*4 + r;
#pragma unroll
        for (int c = 0; c < 4; c++) {
            int n = n0 + tx*4 + c;
            float v = acc[r][c] + cb[n];
            v = v / (1.f + expf(-v));            // silu
            g_qk[(size_t)mm * D2 + n] = v;
        }
    }
}

// ---------------- input/forget gate pre-activations ---------------------------
// itilde = q @ wi_w + wi_b  (q = block-linear output), ftilde = k @ wf_w + wf_b
__global__ void gates_kernel(const float* __restrict__ wi, const float* __restrict__ wib,
                             const float* __restrict__ wf, const float* __restrict__ wfb) {
    int idx = blockIdx.x * blockDim.x + threadIdx.x;   // TOK*NH threads
    int t = idx >> 3, h = idx & 7;
    float si = 0.f, sf = 0.f;
    const float* qr = g_q + (size_t)t * D2;
    const float* kr = g_k + (size_t)t * D2;
    for (int i = 0; i < D2; i++) {
        si = fmaf(qr[i], wi[i*NH + h], si);
        sf = fmaf(kr[i], wf[i*NH + h], sf);
    }
    int b = t >> 11, s = t & (SS - 1);
    g_it[((size_t)b*NH + h)*SS + s] = si + wib[h];
    g_ft[((size_t)b*NH + h)*SS + s] = sf + wfb[h];
}

// ---------------- per-(b,h) scans: cs = cumsum(logsigmoid(f)), m, prefix-max M --
__global__ void scan_kernel() {
    int bh = blockIdx.x;
    int tid = threadIdx.x;
    int lane = tid & 31, w = tid >> 5;
    __shared__ float ws[8], wm[8];
    float carry_s = 0.f, carry_m = -1e30f;
    for (int c0 = 0; c0 < SS; c0 += 256) {
        int j = c0 + tid;
        float f = g_ft[(size_t)bh*SS + j];
        float ls = fminf(f, 0.f) - log1pf(expf(-fabsf(f)));
        // inclusive sum scan
        float v = ls;
#pragma unroll
        for (int o = 1; o < 32; o <<= 1) {
            float u = __shfl_up_sync(0xffffffffu, v, o);
            if (lane >= o) v += u;
        }
        if (lane == 31) ws[w] = v;
        __syncthreads();
        if (tid == 0) { float run = 0.f; for (int i = 0; i < 8; i++) { run += ws[i]; ws[i] = run; } }
        __syncthreads();
        float cs = v + (w ? ws[w-1] : 0.f) + carry_s;
        g_cs[(size_t)bh*SS + j] = cs;
        float m = g_it[(size_t)bh*SS + j] - cs;
        g_mm[(size_t)bh*SS + j] = m;
        // inclusive max scan
        float mv = m;
#pragma unroll
        for (int o = 1; o < 32; o <<= 1) {
            float u = __shfl_up_sync(0xffffffffu, mv, o);
            if (lane >= o) mv = fmaxf(mv, u);
        }
        if (lane == 31) wm[w] = mv;
        __syncthreads();
        if (tid == 0) { float run = -1e30f; for (int i = 0; i < 8; i++) { run = fmaxf(run, wm[i]); wm[i] = run; } }
        __syncthreads();
        float Mpref = fmaxf(mv, w ? wm[w-1] : -1e30f);
        g_Mx[(size_t)bh*SS + j] = fmaxf(Mpref, carry_m);
        carry_s += ws[7];
        carry_m = fmaxf(carry_m, wm[7]);
        __syncthreads();
    }
}

// ---------------- mLSTM attention: H = (C~ @ V) / (max(|rowsum C~|, floor)+eps) -
// D_ij = exp(m_j - M_i) (<=1 for j<=i, no online rescale needed)
#define ATTN_SMEM_FLOATS (64*129 + 8448 + 64*68 + 64 + 64*16 + 64)
__global__ void __launch_bounds__(256) attn_kernel() {
    extern __shared__ float sm[];
    float* Qs  = sm;                    // [64][129]
    float* KV  = Qs + 64*129;           // K: [128][65] transposed; V: [64][132]
    float* Ps  = KV + 8448;             // [64][68]
    float* mms = Ps + 64*68;            // [64]
    float* red = mms + 64;              // [64][16]
    float* inv = red + 64*16;           // [64]

    int bh = blockIdx.y; int b = bh >> 3, h = bh & 7;
    int qt = blockIdx.x; int row0 = qt * 64;
    int tid = threadIdx.x, ty = tid >> 4, tx = tid & 15;
    int tok0 = b * SS + row0;

    for (int i = tid; i < 64*HD; i += 256) {
        int r = i >> 7, d = i & 127;
        Qs[r*129 + d] = g_qh[(size_t)(tok0 + r)*D2 + h*HD + d];
    }
    float Mi[4];
#pragma unroll
    for (int r = 0; r < 4; r++) Mi[r] = g_Mx[(size_t)bh*SS + row0 + ty*4 + r];

    float acc[4][8] = {};
    float rsum[4] = {};
    const float inv_tau = 0.03125f;     // 1/sqrt(1024)

    for (int jt = 0; jt <= qt; jt++) {
        int jr0 = jt * 64;
        __syncthreads();
        // load K transposed: KT[d][r]
        for (int i = tid; i < 64*HD; i += 256) {
            int r = i >> 7, d = i & 127;
            KV[d*65 + r] = g_kh[(size_t)(b*SS + jr0 + r)*D2 + h*HD + d];
        }
        if (tid < 64) mms[tid] = g_mm[(size_t)bh*SS + jr0 + tid];
        __syncthreads();
        // S = Q @ K^T
        float s[4][4] = {};
        for (int d = 0; d < HD; d++) {
            float a[4], bb[4];
#pragma unroll
            for (int r = 0; r < 4; r++) a[r] = Qs[(ty*4 + r)*129 + d];
#pragma unroll
            for (int c = 0; c < 4; c++) bb[c] = KV[d*65 + tx*4 + c];
#pragma unroll
            for (int r = 0; r < 4; r++)
#pragma unroll
                for (int c = 0; c < 4; c++)
                    s[r][c] = fmaf(a[r], bb[c], s[r][c]);
        }
        // scale + causal mask -> P
#pragma unroll
        for (int r = 0; r < 4; r++) {
            int gi = row0 + ty*4 + r;
#pragma unroll
            for (int c = 0; c < 4; c++) {
                int gj = jr0 + tx*4 + c;
                float p = 0.f;
                if (gj <= gi) p = s[r][c] * inv_tau * expf(mms[tx*4 + c] - Mi[r]);
                rsum[r] += p;
                Ps[(ty*4 + r)*68 + tx*4 + c] = p;
            }
        }
        __syncthreads();
        // load V: [r][d]
        for (int i = tid; i < 64*HD; i += 256) {
            int r = i >> 7, d = i & 127;
            KV[r*132 + d] = g_vh[(size_t)(b*SS + jr0 + r)*D2 + h*HD + d];
        }
        __syncthreads();
        // acc += P @ V
        for (int kk = 0; kk < 64; kk++) {
            float a[4];
#pragma unroll
            for (int r = 0; r < 4; r++) a[r] = Ps[(ty*4 + r)*68 + kk];
            float4 b0 = *(const float4*)&KV[kk*132 + tx*8];
            float4 b1 = *(const float4*)&KV[kk*132 + tx*8 + 4];
            float bb[8] = {b0.x, b0.y, b0.z, b0.w, b1.x, b1.y, b1.z, b1.w};
#pragma unroll
            for (int r = 0; r < 4; r++)
#pragma unroll
                for (int c = 0; c < 8; c++)
                    acc[r][c] = fmaf(a[r], bb[c], acc[r][c]);
        }
    }
    // row-sum reduce + denominator
    __syncthreads();
#pragma unroll
    for (int r = 0; r < 4; r++) red[(ty*4 + r)*16 + tx] = rsum[r];
    __syncthreads();
    if (tid < 64) {
        float s2 = 0.f;
#pragma unroll
        for (int i = 0; i < 16; i++) s2 += red[tid*16 + i];
        int gi = row0 + tid;
        float floorv = expf(-g_cs[(size_t)bh*SS + gi] - g_Mx[(size_t)bh*SS + gi]);
        float den = fmaxf(fabsf(s2), floorv) + 1e-8f;
        inv[tid] = 1.f / den;
    }
    __syncthreads();
#pragma unroll
    for (int r = 0; r < 4; r++) {
        float iv = inv[ty*4 + r];
#pragma unroll
        for (int c = 0; c < 8; c++)
            g_Ho[(size_t)(tok0 + ty*4 + r)*D2 + h*HD + tx*8 + c] = acc[r][c] * iv;
    }
}

// ---------------- GroupNorm(heads) + skip*qk, then *bgate ---------------------
__global__ void gn_kernel(const float* __restrict__ gnw, const float* __restrict__ gnb,
                          const float* __restrict__ skip) {
    int g = blockIdx.x * 8 + (threadIdx.x >> 5);   // group = (t, h)
    int lane = threadIdx.x & 31;
    int t = g >> 3, h = g & 7;
    const float* Hr = g_Ho + (size_t)t * D2 + h * HD;
    float4 v4 = *(const float4*)(Hr + lane * 4);
    float vv[4] = {v4.x, v4.y, v4.z, v4.w};
    float s = vv[0] + vv[1] + vv[2] + vv[3];
#pragma unroll
    for (int o = 16; o; o >>= 1) s += __shfl_xor_sync(0xffffffffu, s, o);
    float mu = s * (1.f / HD);
    float q = 0.f;
#pragma unroll
    for (int j = 0; j < 4; j++) { float d = vv[j] - mu; q += d * d; }
#pragma unroll
    for (int o = 16; o; o >>= 1) q += __shfl_xor_sync(0xffffffffu, q, o);
    float rstd = rsqrtf(q * (1.f / HD) + EPSF);
#pragma unroll
    for (int j = 0; j < 4; j++) {
        int c = h * HD + lane * 4 + j;
        float val = (vv[j] - mu) * rstd * gnw[c] + gnb[c];
        val += skip[c] * g_qk[(size_t)t * D2 + c];
        val *= g_bg[(size_t)t * D2 + c];
        g_h2[(size_t)t * D2 + c] = val;
    }
}

// ------------------------------- launcher --------------------------------------
extern "C" void kernel_launch(void* const* d_in, const int* in_sizes, int n_in,
                              void* d_out, int out_size) {
    (void)in_sizes; (void)n_in; (void)out_size;
    const float* x      = (const float*)d_in[0];
    const float* ln_w   = (const float*)d_in[1];
    const float* ln_b   = (const float*)d_in[2];
    const float* mlp1_w = (const float*)d_in[3];
    const float* mlp1_b = (const float*)d_in[4];
    const float* mlp2_w = (const float*)d_in[5];
    const float* mlp2_b = (const float*)d_in[6];
    const float* conv_w = (const float*)d_in[7];
    const float* conv_b = (const float*)d_in[8];
    const float* bq_w   = (const float*)d_in[9];
    const float* bk_w   = (const float*)d_in[10];
    const float* bv_w   = (const float*)d_in[11];
    const float* wq_w   = (const float*)d_in[12];
    const float* wq_b   = (const float*)d_in[13];
    const float* wk_w   = (const float*)d_in[14];
    const float* wk_b   = (const float*)d_in[15];
    const float* wv_w   = (const float*)d_in[16];
    const float* wv_b   = (const float*)d_in[17];
    const float* wi_w   = (const float*)d_in[18];
    const float* wi_b   = (const float*)d_in[19];
    const float* wf_w   = (const float*)d_in[20];
    const float* wf_b   = (const float*)d_in[21];
    const float* gn_w   = (const float*)d_in[22];
    const float* gn_b   = (const float*)d_in[23];
    const float* skip   = (const float*)d_in[24];
    const float* fin_w  = (const float*)d_in[25];
    const float* fin_b  = (const float*)d_in[26];

    float *xn, *a, *bg, *qk, *q, *k, *v, *qh, *kh, *vh, *h2;
    cudaGetSymbolAddress((void**)&xn, g_xn);
    cudaGetSymbolAddress((void**)&a,  g_a);
    cudaGetSymbolAddress((void**)&bg, g_bg);
    cudaGetSymbolAddress((void**)&qk, g_qk);
    cudaGetSymbolAddress((void**)&q,  g_q);
    cudaGetSymbolAddress((void**)&k,  g_k);
    cudaGetSymbolAddress((void**)&v,  g_v);
    cudaGetSymbolAddress((void**)&qh, g_qh);
    cudaGetSymbolAddress((void**)&kh, g_kh);
    cudaGetSymbolAddress((void**)&vh, g_vh);
    cudaGetSymbolAddress((void**)&h2, g_h2);

    // weight transpose for conv (recomputed every call; deterministic)
    conv_tr<<<(KSZ*D2*D2 + 255)/256, 256>>>(conv_w);

    // layernorm
    ln_kernel<<<TOK/8, 256>>>(x, ln_w, ln_b);

    dim3 gD2(D2/64, TOK/64);
    sgemm_kernel<0><<<gD2, 256>>>(xn, D1, mlp1_w, D2, mlp1_b, nullptr, 0, a,  D2, TOK, D2, D1);
    sgemm_kernel<1><<<gD2, 256>>>(xn, D1, mlp2_w, D2, mlp2_b, nullptr, 0, bg, D2, TOK, D2, D1);

    // causal conv + silu -> qk
    conv_gemm<<<gD2, 256>>>(conv_b);

    // block-diagonal linears (4 groups each)
    dim3 gBL(BLKG/64, TOK/64);
    for (int g = 0; g < NBG; g++) {
        sgemm_kernel<0><<<gBL, 256>>>(qk + g*BLKG, D2, bq_w + (size_t)g*BLKG*BLKG, BLKG,
                                      nullptr, nullptr, 0, q + g*BLKG, D2, TOK, BLKG, BLKG);
        sgemm_kernel<0><<<gBL, 256>>>(qk + g*BLKG, D2, bk_w + (size_t)g*BLKG*BLKG, BLKG,
                                      nullptr, nullptr, 0, k + g*BLKG, D2, TOK, BLKG, BLKG);
        sgemm_kernel<0><<<gBL, 256>>>(a  + g*BLKG, D2, bv_w + (size_t)g*BLKG*BLKG, BLKG,
                                      nullptr, nullptr, 0, v + g*BLKG, D2, TOK, BLKG, BLKG);
    }

    // dense projections
    sgemm_kernel<0><<<gD2, 256>>>(q, D2, wq_w, D2, wq_b, nullptr, 0, qh, D2, TOK, D2, D2);
    sgemm_kernel<0><<<gD2, 256>>>(k, D2, wk_w, D2, wk_b, nullptr, 0, kh, D2, TOK, D2, D2);
    sgemm_kernel<0><<<gD2, 256>>>(v, D2, wv_w, D2, wv_b, nullptr, 0, vh, D2, TOK, D2, D2);

    // gates + scans
    gates_kernel<<<TOK*NH/256, 256>>>(wi_w, wi_b, wf_w, wf_b);
    scan_kernel<<<BB*NH, 256>>>();

    // attention
    const int attn_smem = ATTN_SMEM_FLOATS * 4;
    cudaFuncSetAttribute(attn_kernel, cudaFuncAttributeMaxDynamicSharedMemorySize, attn_smem);
    attn_kernel<<<dim3(SS/64, BB*NH), 256, attn_smem>>>();

    // groupnorm + skip + gate
    gn_kernel<<<TOK*NH/8, 256>>>(gn_w, gn_b, skip);

    // final GEMM + residual -> d_out
    dim3 gF(D1/64, TOK/64);
    sgemm_kernel<2><<<gF, 256>>>(h2, D2, fin_w, D1, fin_b, x, D1,
                                 (float*)d_out, D1, TOK, D1, D2);
}

// round 2
// speedup vs baseline: 2.9949x; 2.9949x over previous
#include <cuda_runtime.h>
#include <math.h>

#define TOK  4096
#define BB   2
#define SS   2048
#define D1   512
#define D2   1024
#define NH   8
#define HD   128
#define NBG  4
#define BLKG 256
#define KSZ  4
#define EPSF 1e-5f

// ---------------- scratch (device globals; no allocation allowed) -------------
static __device__ float g_xn[TOK*D1];
static __device__ float g_a [TOK*D2];
static __device__ float g_bg[TOK*D2];
static __device__ float g_qk[TOK*D2];
static __device__ float g_q [TOK*D2];
static __device__ float g_k [TOK*D2];
static __device__ float g_v [TOK*D2];
static __device__ float g_qh[TOK*D2];
static __device__ float g_kh[TOK*D2];
static __device__ float g_vh[TOK*D2];
static __device__ float g_Ho[TOK*D2];
static __device__ float g_h2[TOK*D2];
static __device__ float g_wc[KSZ*D2*D2];
static __device__ float g_it[BB*NH*SS];
static __device__ float g_ft[BB*NH*SS];
static __device__ float g_cs[BB*NH*SS];
static __device__ float g_mm[BB*NH*SS];
static __device__ float g_Mx[BB*NH*SS];
static __device__ float g_mtmax[BB*NH*32];   // per-(bh, 64-tile) max of m

// ---------------- tf32 helpers ------------------------------------------------
__device__ __forceinline__ unsigned f2tf(float x){
    unsigned r; asm("cvt.rna.tf32.f32 %0, %1;" : "=r"(r) : "f"(x)); return r;
}
__device__ __forceinline__ void mma8(float* d, const unsigned* a, const unsigned* b){
    asm volatile("mma.sync.aligned.m16n8k8.row.col.f32.tf32.tf32.f32 "
        "{%0,%1,%2,%3}, {%4,%5,%6,%7}, {%8,%9}, {%0,%1,%2,%3};\n"
        : "+f"(d[0]), "+f"(d[1]), "+f"(d[2]), "+f"(d[3])
        : "r"(a[0]), "r"(a[1]), "r"(a[2]), "r"(a[3]), "r"(b[0]), "r"(b[1]));
}
__device__ __forceinline__ float silu_f(float x){ return x / (1.f + __expf(-x)); }

// ---------------- layernorm over last dim (512), warp per token ---------------
__global__ void ln_kernel(const float* __restrict__ x,
                          const float* __restrict__ w,
                          const float* __restrict__ b) {
    int t = blockIdx.x * 8 + (threadIdx.x >> 5);
    int lane = threadIdx.x & 31;
    const float* xr = x + (size_t)t * D1;
    float v[16]; float s = 0.f;
#pragma unroll
    for (int i = 0; i < 16; i++) { v[i] = xr[lane + 32*i]; s += v[i]; }
#pragma unroll
    for (int o = 16; o; o >>= 1) s += __shfl_xor_sync(0xffffffffu, s, o);
    float mu = s * (1.f / D1);
    float q = 0.f;
#pragma unroll
    for (int i = 0; i < 16; i++) { float d = v[i] - mu; q += d * d; }
#pragma unroll
    for (int o = 16; o; o >>= 1) q += __shfl_xor_sync(0xffffffffu, q, o);
    float rstd = rsqrtf(q * (1.f / D1) + EPSF);
#pragma unroll
    for (int i = 0; i < 16; i++) {
        int c = lane + 32*i;
        g_xn[(size_t)t*D1 + c] = (v[i] - mu) * rstd * w[c] + b[c];
    }
}

// ---------------- TF32 tensor-core GEMM: C = act(A@B + bias)(+res) -------------
// 128x128 tile, BK=16, 256 threads (8 warps in 2x4), warp tile 64x32.
// ACT: 0 none, 1 silu, 2 add residual.
template<int ACT>
__global__ void __launch_bounds__(256) tgemm(
    const float* __restrict__ A, int lda,
    const float* __restrict__ B, int ldb,
    const float* __restrict__ bias,
    const float* __restrict__ res, int ldr,
    float* __restrict__ C, int ldc, int K)
{
    __shared__ float As[2][16][136];   // k-major (transposed), pad 8 -> conflict-free frag loads
    __shared__ float Bs[2][16][136];
    const int tid = threadIdx.x;
    const int m0 = blockIdx.y * 128, n0 = blockIdx.x * 128;
    const int arow = tid >> 2, acol = (tid & 3) * 4;
    const int brow = tid >> 5, bcol = (tid & 31) * 4;
    const int lane = tid & 31, warp = tid >> 5;
    const int grp = lane >> 2, qid = lane & 3;
    const int wm = (warp & 1) * 64, wn = (warp >> 1) * 32;

    const float* Ap0 = A + (size_t)(m0 + arow) * lda + acol;
    const float* Ap1 = A + (size_t)(m0 + arow + 64) * lda + acol;
    const float* Bp0 = B + (size_t)brow * ldb + n0 + bcol;
    const float* Bp1 = B + (size_t)(brow + 8) * ldb + n0 + bcol;

    float acc[4][4][4] = {};
    const int nkt = K >> 4;

    // preload tile 0
    {
        float4 a0 = *(const float4*)Ap0;
        float4 a1 = *(const float4*)Ap1;
        float4 b0 = *(const float4*)Bp0;
        float4 b1 = *(const float4*)Bp1;
        As[0][acol+0][arow] = __uint_as_float(f2tf(a0.x));
        As[0][acol+1][arow] = __uint_as_float(f2tf(a0.y));
        As[0][acol+2][arow] = __uint_as_float(f2tf(a0.z));
        As[0][acol+3][arow] = __uint_as_float(f2tf(a0.w));
        As[0][acol+0][arow+64] = __uint_as_float(f2tf(a1.x));
        As[0][acol+1][arow+64] = __uint_as_float(f2tf(a1.y));
        As[0][acol+2][arow+64] = __uint_as_float(f2tf(a1.z));
        As[0][acol+3][arow+64] = __uint_as_float(f2tf(a1.w));
        float4 c0 = make_float4(__uint_as_float(f2tf(b0.x)), __uint_as_float(f2tf(b0.y)),
                                __uint_as_float(f2tf(b0.z)), __uint_as_float(f2tf(b0.w)));
        float4 c1 = make_float4(__uint_as_float(f2tf(b1.x)), __uint_as_float(f2tf(b1.y)),
                                __uint_as_float(f2tf(b1.z)), __uint_as_float(f2tf(b1.w)));
        *(float4*)&Bs[0][brow][bcol]   = c0;
        *(float4*)&Bs[0][brow+8][bcol] = c1;
    }

    int cur = 0;
    for (int kt = 0; kt < nkt; kt++) {
        float4 na0, na1, nb0, nb1;
        if (kt + 1 < nkt) {
            na0 = *(const float4*)(Ap0 + (kt + 1) * 16);
            na1 = *(const float4*)(Ap1 + (kt + 1) * 16);
            nb0 = *(const float4*)(Bp0 + (size_t)(kt + 1) * 16 * ldb);
            nb1 = *(const float4*)(Bp1 + (size_t)(kt + 1) * 16 * ldb);
        }
        __syncthreads();
#pragma unroll
        for (int kk = 0; kk < 16; kk += 8) {
            unsigned aF[4][4], bF[4][2];
#pragma unroll
            for (int mi = 0; mi < 4; mi++) {
                int m = wm + mi * 16 + grp;
                aF[mi][0] = __float_as_uint(As[cur][kk+qid][m]);
                aF[mi][1] = __float_as_uint(As[cur][kk+qid][m+8]);
                aF[mi][2] = __float_as_uint(As[cur][kk+qid+4][m]);
                aF[mi][3] = __float_as_uint(As[cur][kk+qid+4][m+8]);
            }
#pragma unroll
            for (int ni = 0; ni < 4; ni++) {
                int n = wn + ni * 8 + grp;
                bF[ni][0] = __float_as_uint(Bs[cur][kk+qid][n]);
                bF[ni][1] = __float_as_uint(Bs[cur][kk+qid+4][n]);
            }
#pragma unroll
            for (int mi = 0; mi < 4; mi++)
#pragma unroll
                for (int ni = 0; ni < 4; ni++)
                    mma8(acc[mi][ni], aF[mi], bF[ni]);
        }
        if (kt + 1 < nkt) {
            int nxt = cur ^ 1;
            As[nxt][acol+0][arow] = __uint_as_float(f2tf(na0.x));
            As[nxt][acol+1][arow] = __uint_as_float(f2tf(na0.y));
            As[nxt][acol+2][arow] = __uint_as_float(f2tf(na0.z));
            As[nxt][acol+3][arow] = __uint_as_float(f2tf(na0.w));
            As[nxt][acol+0][arow+64] = __uint_as_float(f2tf(na1.x));
            As[nxt][acol+1][arow+64] = __uint_as_float(f2tf(na1.y));
            As[nxt][acol+2][arow+64] = __uint_as_float(f2tf(na1.z));
            As[nxt][acol+3][arow+64] = __uint_as_float(f2tf(na1.w));
            float4 c0 = make_float4(__uint_as_float(f2tf(nb0.x)), __uint_as_float(f2tf(nb0.y)),
                                    __uint_as_float(f2tf(nb0.z)), __uint_as_float(f2tf(nb0.w)));
            float4 c1 = make_float4(__uint_as_float(f2tf(nb1.x)), __uint_as_float(f2tf(nb1.y)),
                                    __uint_as_float(f2tf(nb1.z)), __uint_as_float(f2tf(nb1.w)));
            *(float4*)&Bs[nxt][brow][bcol]   = c0;
            *(float4*)&Bs[nxt][brow+8][bcol] = c1;
            cur = nxt;
        }
    }

#pragma unroll
    for (int mi = 0; mi < 4; mi++) {
        int r0 = m0 + wm + mi * 16 + grp;
#pragma unroll
        for (int ni = 0; ni < 4; ni++) {
            int c = n0 + wn + ni * 8 + qid * 2;
            float b0 = 0.f, b1 = 0.f;
            if (bias) { b0 = bias[c]; b1 = bias[c+1]; }
            float v0 = acc[mi][ni][0] + b0, v1 = acc[mi][ni][1] + b1;
            float v2 = acc[mi][ni][2] + b0, v3 = acc[mi][ni][3] + b1;
            if (ACT == 1) { v0 = silu_f(v0); v1 = silu_f(v1); v2 = silu_f(v2); v3 = silu_f(v3); }
            if (ACT == 2) {
                v0 += res[(size_t)r0*ldr + c];     v1 += res[(size_t)r0*ldr + c + 1];
                v2 += res[(size_t)(r0+8)*ldr + c]; v3 += res[(size_t)(r0+8)*ldr + c + 1];
            }
            float2 p0 = make_float2(v0, v1), p1 = make_float2(v2, v3);
            *(float2*)(C + (size_t)r0*ldc + c)     = p0;
            *(float2*)(C + (size_t)(r0+8)*ldc + c) = p1;
        }
    }
}

// ---------------- conv_w [O,I,K] -> g_wc [K][I][O] ---------------------------
__global__ void conv_tr(const float* __restrict__ cw) {
    int idx = blockIdx.x * 256 + threadIdx.x;
    if (idx >= KSZ * D2 * D2) return;
    int o   = idx >> 12;
    int rem = idx & 4095;
    int i   = rem >> 2;
    int kk  = rem & 3;
    g_wc[((size_t)kk * D2 + i) * D2 + o] = cw[idx];
}

// ---------------- causal conv1d as one K=4096 TF32 GEMM + bias + silu ----------
// A_ext[m][kc*1024+i] = a[(m+kc-3)][i] (zero-padded), B_ext = g_wc
__global__ void __launch_bounds__(256) tconv(const float* __restrict__ cb)
{
    __shared__ float As[2][16][136];
    __shared__ float Bs[2][16][136];
    const int tid = threadIdx.x;
    const int m0 = blockIdx.y * 128, n0 = blockIdx.x * 128;
    const int arow = tid >> 2, acol = (tid & 3) * 4;
    const int brow = tid >> 5, bcol = (tid & 31) * 4;
    const int lane = tid & 31, warp = tid >> 5;
    const int grp = lane >> 2, qid = lane & 3;
    const int wm = (warp & 1) * 64, wn = (warp >> 1) * 32;
    const int sl0 = (m0 + arow) & (SS - 1);     // row arow; row arow+64 always valid

    float acc[4][4][4] = {};
    const int nkt = (KSZ * D2) >> 4;            // 256

    float4 zz = make_float4(0.f, 0.f, 0.f, 0.f);

#define CONV_LOAD(KT, A0, A1, B0, B1)                                               \
    {                                                                               \
        int kc  = (KT) >> 6;                                                        \
        int kin = ((KT) & 63) * 16;                                                 \
        bool ok0 = (sl0 + kc) >= 3;                                                 \
        const float* ar0 = g_a + (size_t)(m0 + arow + kc - 3) * D2 + kin + acol;    \
        const float* ar1 = g_a + (size_t)(m0 + arow + 64 + kc - 3) * D2 + kin + acol;\
        A0 = ok0 ? *(const float4*)ar0 : zz;                                        \
        A1 = *(const float4*)ar1;                                                   \
        const float* br = g_wc + (size_t)((kc << 10) + kin + brow) * D2 + n0 + bcol;\
        B0 = *(const float4*)br;                                                    \
        B1 = *(const float4*)(br + 8 * D2);                                         \
    }

#define SMEM_STORE(BUF, A0, A1, B0, B1)                                             \
    {                                                                               \
        As[BUF][acol+0][arow] = __uint_as_float(f2tf(A0.x));                        \
        As[BUF][acol+1][arow] = __uint_as_float(f2tf(A0.y));                        \
        As[BUF][acol+2][arow] = __uint_as_float(f2tf(A0.z));                        \
        As[BUF][acol+3][arow] = __uint_as_float(f2tf(A0.w));                        \
        As[BUF][acol+0][arow+64] = __uint_as_float(f2tf(A1.x));                     \
        As[BUF][acol+1][arow+64] = __uint_as_float(f2tf(A1.y));                     \
        As[BUF][acol+2][arow+64] = __uint_as_float(f2tf(A1.z));                     \
        As[BUF][acol+3][arow+64] = __uint_as_float(f2tf(A1.w));                     \
        float4 c0 = make_float4(__uint_as_float(f2tf(B0.x)), __uint_as_float(f2tf(B0.y)), \
                                __uint_as_float(f2tf(B0.z)), __uint_as_float(f2tf(B0.w))); \
        float4 c1 = make_float4(__uint_as_float(f2tf(B1.x)), __uint_as_float(f2tf(B1.y)), \
                                __uint_as_float(f2tf(B1.z)), __uint_as_float(f2tf(B1.w))); \
        *(float4*)&Bs[BUF][brow][bcol]   = c0;                                      \
        *(float4*)&Bs[BUF][brow+8][bcol] = c1;                                      \
    }

    {
        float4 a0, a1, b0, b1;
        CONV_LOAD(0, a0, a1, b0, b1);
        SMEM_STORE(0, a0, a1, b0, b1);
    }
    int cur = 0;
    for (int kt = 0; kt < nkt; kt++) {
        float4 na0, na1, nb0, nb1;
        if (kt + 1 < nkt) CONV_LOAD(kt + 1, na0, na1, nb0, nb1);
        __syncthreads();
#pragma unroll
        for (int kk = 0; kk < 16; kk += 8) {
            unsigned aF[4][4], bF[4][2];
#pragma unroll
            for (int mi = 0; mi < 4; mi++) {
                int m = wm + mi * 16 + grp;
                aF[mi][0] = __float_as_uint(As[cur][kk+qid][m]);
                aF[mi][1] = __float_as_uint(As[cur][kk+qid][m+8]);
                aF[mi][2] = __float_as_uint(As[cur][kk+qid+4][m]);
                aF[mi][3] = __float_as_uint(As[cur][kk+qid+4][m+8]);
            }
#pragma unroll
            for (int ni = 0; ni < 4; ni++) {
                int n = wn + ni * 8 + grp;
                bF[ni][0] = __float_as_uint(Bs[cur][kk+qid][n]);
                bF[ni][1] = __float_as_uint(Bs[cur][kk+qid+4][n]);
            }
#pragma unroll
            for (int mi = 0; mi < 4; mi++)
#pragma unroll
                for (int ni = 0; ni < 4; ni++)
                    mma8(acc[mi][ni], aF[mi], bF[ni]);
        }
        if (kt + 1 < nkt) {
            int nxt = cur ^ 1;
            SMEM_STORE(nxt, na0, na1, nb0, nb1);
            cur = nxt;
        }
    }

#pragma unroll
    for (int mi = 0; mi < 4; mi++) {
        int r0 = m0 + wm + mi * 16 + grp;
#pragma unroll
        for (int ni = 0; ni < 4; ni++) {
            int c = n0 + wn + ni * 8 + qid * 2;
            float b0 = cb[c], b1 = cb[c+1];
            float v0 = silu_f(acc[mi][ni][0] + b0), v1 = silu_f(acc[mi][ni][1] + b1);
            float v2 = silu_f(acc[mi][ni][2] + b0), v3 = silu_f(acc[mi][ni][3] + b1);
            float2 p0 = make_float2(v0, v1), p1 = make_float2(v2, v3);
            *(float2*)(g_qk + (size_t)r0*D2 + c)     = p0;
            *(float2*)(g_qk + (size_t)(r0+8)*D2 + c) = p1;
        }
    }
#undef CONV_LOAD
#undef SMEM_STORE
}

// ---------------- input/forget gate pre-activations ---------------------------
__global__ void gates_kernel(const float* __restrict__ wi, const float* __restrict__ wib,
                             const float* __restrict__ wf, const float* __restrict__ wfb) {
    int idx = blockIdx.x * blockDim.x + threadIdx.x;   // TOK*NH threads
    int t = idx >> 3, h = idx & 7;
    float si = 0.f, sf = 0.f;
    const float* qr = g_q + (size_t)t * D2;
    const float* kr = g_k + (size_t)t * D2;
    for (int i = 0; i < D2; i++) {
        si = fmaf(qr[i], wi[i*NH + h], si);
        sf = fmaf(kr[i], wf[i*NH + h], sf);
    }
    int b = t >> 11, s = t & (SS - 1);
    g_it[((size_t)b*NH + h)*SS + s] = si + wib[h];
    g_ft[((size_t)b*NH + h)*SS + s] = sf + wfb[h];
}

// ---------------- per-(b,h) scans ----------------------------------------------
__global__ void scan_kernel() {
    int bh = blockIdx.x;
    int tid = threadIdx.x;
    int lane = tid & 31, w = tid >> 5;
    __shared__ float ws[8], wm[8];
    float carry_s = 0.f, carry_m = -1e30f;
    for (int c0 = 0; c0 < SS; c0 += 256) {
        int j = c0 + tid;
        float f = g_ft[(size_t)bh*SS + j];
        float ls = fminf(f, 0.f) - log1pf(expf(-fabsf(f)));
        float v = ls;
#pragma unroll
        for (int o = 1; o < 32; o <<= 1) {
            float u = __shfl_up_sync(0xffffffffu, v, o);
            if (lane >= o) v += u;
        }
        if (lane == 31) ws[w] = v;
        __syncthreads();
        if (tid == 0) { float run = 0.f; for (int i = 0; i < 8; i++) { run += ws[i]; ws[i] = run; } }
        __syncthreads();
        float cs = v + (w ? ws[w-1] : 0.f) + carry_s;
        g_cs[(size_t)bh*SS + j] = cs;
        float m = g_it[(size_t)bh*SS + j] - cs;
        g_mm[(size_t)bh*SS + j] = m;
        float mv = m;
#pragma unroll
        for (int o = 1; o < 32; o <<= 1) {
            float u = __shfl_up_sync(0xffffffffu, mv, o);
            if (lane >= o) mv = fmaxf(mv, u);
        }
        if (lane == 31) wm[w] = mv;
        __syncthreads();
        if (tid == 0) { float run = -1e30f; for (int i = 0; i < 8; i++) { run = fmaxf(run, wm[i]); wm[i] = run; } }
        __syncthreads();
        float Mpref = fmaxf(mv, w ? wm[w-1] : -1e30f);
        g_Mx[(size_t)bh*SS + j] = fmaxf(Mpref, carry_m);
        carry_s += ws[7];
        carry_m = fmaxf(carry_m, wm[7]);
        __syncthreads();
    }
}

// ---------------- per-64-tile maxima of m (for attention tile skip) ------------
__global__ void tilemax_kernel() {
    int bh = blockIdx.x;
    int t  = threadIdx.x;     // 32 tiles
    float mx = -1e30f;
    const float* mr = g_mm + (size_t)bh*SS + t*64;
    for (int i = 0; i < 64; i++) mx = fmaxf(mx, mr[i]);
    g_mtmax[bh*32 + t] = mx;
}

// ---------------- mLSTM attention with decay tile skip -------------------------
#define ATTN_SMEM_FLOATS (64*129 + 8448 + 64*68 + 64 + 64*16 + 64)
__global__ void __launch_bounds__(256) attn_kernel() {
    extern __shared__ float sm[];
    float* Qs  = sm;                    // [64][129]
    float* KV  = Qs + 64*129;           // K: [128][65] transposed; V: [64][132]
    float* Ps  = KV + 8448;             // [64][68]
    float* mms = Ps + 64*68;            // [64]
    float* red = mms + 64;              // [64][16]
    float* inv = red + 64*16;           // [64]

    int bh = blockIdx.y; int b = bh >> 3, h = bh & 7;
    int qt = blockIdx.x; int row0 = qt * 64;
    int tid = threadIdx.x, ty = tid >> 4, tx = tid & 15;
    int tok0 = b * SS + row0;

    for (int i = tid; i < 64*HD; i += 256) {
        int r = i >> 7, d = i & 127;
        Qs[r*129 + d] = g_qh[(size_t)(tok0 + r)*D2 + h*HD + d];
    }
    float Mi[4];
#pragma unroll
    for (int r = 0; r < 4; r++) Mi[r] = g_Mx[(size_t)bh*SS + row0 + ty*4 + r];
    float Mtop = g_Mx[(size_t)bh*SS + row0];   // min over tile (M nondecreasing)

    float acc[4][8] = {};
    float rsum[4] = {};
    const float inv_tau = 0.03125f;     // 1/sqrt(1024)

    for (int jt = 0; jt <= qt; jt++) {
        // tiles whose max decay exponent is < Mtop-35 contribute < 6e-16 relatively
        if (jt < qt && g_mtmax[bh*32 + jt] < Mtop - 35.f) continue;
        int jr0 = jt * 64;
        __syncthreads();
        for (int i = tid; i < 64*HD; i += 256) {
            int r = i >> 7, d = i & 127;
            KV[d*65 + r] = g_kh[(size_t)(b*SS + jr0 + r)*D2 + h*HD + d];
        }
        if (tid < 64) mms[tid] = g_mm[(size_t)bh*SS + jr0 + tid];
        __syncthreads();
        float s[4][4] = {};
        for (int d = 0; d < HD; d++) {
            float a[4], bb[4];
#pragma unroll
            for (int r = 0; r < 4; r++) a[r] = Qs[(ty*4 + r)*129 + d];
#pragma unroll
            for (int c = 0; c < 4; c++) bb[c] = KV[d*65 + tx*4 + c];
#pragma unroll
            for (int r = 0; r < 4; r++)
#pragma unroll
                for (int c = 0; c < 4; c++)
                    s[r][c] = fmaf(a[r], bb[c], s[r][c]);
        }
#pragma unroll
        for (int r = 0; r < 4; r++) {
            int gi = row0 + ty*4 + r;
#pragma unroll
            for (int c = 0; c < 4; c++) {
                int gj = jr0 + tx*4 + c;
                float p = 0.f;
                if (gj <= gi) p = s[r][c] * inv_tau * expf(mms[tx*4 + c] - Mi[r]);
                rsum[r] += p;
                Ps[(ty*4 + r)*68 + tx*4 + c] = p;
            }
        }
        __syncthreads();
        for (int i = tid; i < 64*HD; i += 256) {
            int r = i >> 7, d = i & 127;
            KV[r*132 + d] = g_vh[(size_t)(b*SS + jr0 + r)*D2 + h*HD + d];
        }
        __syncthreads();
        for (int kk = 0; kk < 64; kk++) {
            float a[4];
#pragma unroll
            for (int r = 0; r < 4; r++) a[r] = Ps[(ty*4 + r)*68 + kk];
            float4 b0 = *(const float4*)&KV[kk*132 + tx*8];
            float4 b1 = *(const float4*)&KV[kk*132 + tx*8 + 4];
            float bb[8] = {b0.x, b0.y, b0.z, b0.w, b1.x, b1.y, b1.z, b1.w};
#pragma unroll
            for (int r = 0; r < 4; r++)
#pragma unroll
                for (int c = 0; c < 8; c++)
                    acc[r][c] = fmaf(a[r], bb[c], acc[r][c]);
        }
    }
    __syncthreads();
#pragma unroll
    for (int r = 0; r < 4; r++) red[(ty*4 + r)*16 + tx] = rsum[r];
    __syncthreads();
    if (tid < 64) {
        float s2 = 0.f;
#pragma unroll
        for (int i = 0; i < 16; i++) s2 += red[tid*16 + i];
        int gi = row0 + tid;
        float floorv = expf(-g_cs[(size_t)bh*SS + gi] - g_Mx[(size_t)bh*SS + gi]);
        float den = fmaxf(fabsf(s2), floorv) + 1e-8f;
        inv[tid] = 1.f / den;
    }
    __syncthreads();
#pragma unroll
    for (int r = 0; r < 4; r++) {
        float iv = inv[ty*4 + r];
#pragma unroll
        for (int c = 0; c < 8; c++)
            g_Ho[(size_t)(tok0 + ty*4 + r)*D2 + h*HD + tx*8 + c] = acc[r][c] * iv;
    }
}

// ---------------- GroupNorm(heads) + skip*qk, then *bgate ---------------------
__global__ void gn_kernel(const float* __restrict__ gnw, const float* __restrict__ gnb,
                          const float* __restrict__ skip) {
    int g = blockIdx.x * 8 + (threadIdx.x >> 5);
    int lane = threadIdx.x & 31;
    int t = g >> 3, h = g & 7;
    const float* Hr = g_Ho + (size_t)t * D2 + h * HD;
    float4 v4 = *(const float4*)(Hr + lane * 4);
    float vv[4] = {v4.x, v4.y, v4.z, v4.w};
    float s = vv[0] + vv[1] + vv[2] + vv[3];
#pragma unroll
    for (int o = 16; o; o >>= 1) s += __shfl_xor_sync(0xffffffffu, s, o);
    float mu = s * (1.f / HD);
    float q = 0.f;
#pragma unroll
    for (int j = 0; j < 4; j++) { float d = vv[j] - mu; q += d * d; }
#pragma unroll
    for (int o = 16; o; o >>= 1) q += __shfl_xor_sync(0xffffffffu, q, o);
    float rstd = rsqrtf(q * (1.f / HD) + EPSF);
#pragma unroll
    for (int j = 0; j < 4; j++) {
        int c = h * HD + lane * 4 + j;
        float val = (vv[j] - mu) * rstd * gnw[c] + gnb[c];
        val += skip[c] * g_qk[(size_t)t * D2 + c];
        val *= g_bg[(size_t)t * D2 + c];
        g_h2[(size_t)t * D2 + c] = val;
    }
}

// ------------------------------- launcher --------------------------------------
extern "C" void kernel_launch(void* const* d_in, const int* in_sizes, int n_in,
                              void* d_out, int out_size) {
    (void)in_sizes; (void)n_in; (void)out_size;
    const float* x      = (const float*)d_in[0];
    const float* ln_w   = (const float*)d_in[1];
    const float* ln_b   = (const float*)d_in[2];
    const float* mlp1_w = (const float*)d_in[3];
    const float* mlp1_b = (const float*)d_in[4];
    const float* mlp2_w = (const float*)d_in[5];
    const float* mlp2_b = (const float*)d_in[6];
    const float* conv_w = (const float*)d_in[7];
    const float* conv_b = (const float*)d_in[8];
    const float* bq_w   = (const float*)d_in[9];
    const float* bk_w   = (const float*)d_in[10];
    const float* bv_w   = (const float*)d_in[11];
    const float* wq_w   = (const float*)d_in[12];
    const float* wq_b   = (const float*)d_in[13];
    const float* wk_w   = (const float*)d_in[14];
    const float* wk_b   = (const float*)d_in[15];
    const float* wv_w   = (const float*)d_in[16];
    const float* wv_b   = (const float*)d_in[17];
    const float* wi_w   = (const float*)d_in[18];
    const float* wi_b   = (const float*)d_in[19];
    const float* wf_w   = (const float*)d_in[20];
    const float* wf_b   = (const float*)d_in[21];
    const float* gn_w   = (const float*)d_in[22];
    const float* gn_b   = (const float*)d_in[23];
    const float* skip   = (const float*)d_in[24];
    const float* fin_w  = (const float*)d_in[25];
    const float* fin_b  = (const float*)d_in[26];

    float *xn, *a, *qk, *q, *k, *v, *qh, *kh, *vh, *h2, *bg;
    cudaGetSymbolAddress((void**)&xn, g_xn);
    cudaGetSymbolAddress((void**)&a,  g_a);
    cudaGetSymbolAddress((void**)&bg, g_bg);
    cudaGetSymbolAddress((void**)&qk, g_qk);
    cudaGetSymbolAddress((void**)&q,  g_q);
    cudaGetSymbolAddress((void**)&k,  g_k);
    cudaGetSymbolAddress((void**)&v,  g_v);
    cudaGetSymbolAddress((void**)&qh, g_qh);
    cudaGetSymbolAddress((void**)&kh, g_kh);
    cudaGetSymbolAddress((void**)&vh, g_vh);
    cudaGetSymbolAddress((void**)&h2, g_h2);

    conv_tr<<<(KSZ*D2*D2 + 255)/256, 256>>>(conv_w);
    ln_kernel<<<TOK/8, 256>>>(x, ln_w, ln_b);

    dim3 gD2(D2/128, TOK/128);          // (8, 32)
    tgemm<0><<<gD2, 256>>>(xn, D1, mlp1_w, D2, mlp1_b, nullptr, 0, a,  D2, D1);
    tgemm<1><<<gD2, 256>>>(xn, D1, mlp2_w, D2, mlp2_b, nullptr, 0, bg, D2, D1);

    // causal conv (K=4096 virtual GEMM) + bias + silu -> qk
    tconv<<<gD2, 256>>>(conv_b);

    // block-diagonal linears
    dim3 gBL(BLKG/128, TOK/128);        // (2, 32)
    for (int g = 0; g < NBG; g++) {
        tgemm<0><<<gBL, 256>>>(qk + g*BLKG, D2, bq_w + (size_t)g*BLKG*BLKG, BLKG,
                               nullptr, nullptr, 0, q + g*BLKG, D2, BLKG);
        tgemm<0><<<gBL, 256>>>(qk + g*BLKG, D2, bk_w + (size_t)g*BLKG*BLKG, BLKG,
                               nullptr, nullptr, 0, k + g*BLKG, D2, BLKG);
        tgemm<0><<<gBL, 256>>>(a  + g*BLKG, D2, bv_w + (size_t)g*BLKG*BLKG, BLKG,
                               nullptr, nullptr, 0, v + g*BLKG, D2, BLKG);
    }

    // dense projections
    tgemm<0><<<gD2, 256>>>(q, D2, wq_w, D2, wq_b, nullptr, 0, qh, D2, D2);
    tgemm<0><<<gD2, 256>>>(k, D2, wk_w, D2, wk_b, nullptr, 0, kh, D2, D2);
    tgemm<0><<<gD2, 256>>>(v, D2, wv_w, D2, wv_b, nullptr, 0, vh, D2, D2);

    // gates + scans + tile maxima
    gates_kernel<<<TOK*NH/256, 256>>>(wi_w, wi_b, wf_w, wf_b);
    scan_kernel<<<BB*NH, 256>>>();
    tilemax_kernel<<<BB*NH, 32>>>();

    // attention
    const int attn_smem = ATTN_SMEM_FLOATS * 4;
    cudaFuncSetAttribute(attn_kernel, cudaFuncAttributeMaxDynamicSharedMemorySize, attn_smem);
    attn_kernel<<<dim3(SS/64, BB*NH), 256, attn_smem>>>();

    gn_kernel<<<TOK*NH/8, 256>>>(gn_w, gn_b, skip);

    // final GEMM + residual -> d_out
    dim3 gF(D1/128, TOK/128);           // (4, 32)
    tgemm<2><<<gF, 256>>>(h2, D2, fin_w, D1, fin_b, x, D1,
                          (float*)d_out, D1, D2);
}

// round 4
// speedup vs baseline: 4.0132x; 1.3400x over previous
#include <cuda_runtime.h>
#include <math.h>

#define TOK  4096
#define BB   2
#define SS   2048
#define D1   512
#define D2   1024
#define NH   8
#define HD   128
#define NBG  4
#define BLKG 256
#define KSZ  4
#define EPSF 1e-5f

// ---------------- scratch (device globals; no allocation allowed) -------------
static __device__ float g_xn[TOK*D1];
static __device__ float g_a [TOK*D2];
static __device__ float g_bg[TOK*D2];
static __device__ float g_qk[TOK*D2];
static __device__ float g_qh[TOK*D2];
static __device__ float g_kh[TOK*D2];
static __device__ float g_vh[TOK*D2];
static __device__ float g_Ho[TOK*D2];
static __device__ float g_h2[TOK*D2];
static __device__ float g_wc[KSZ*D2*D2];
static __device__ float g_Wq[D2*D2];
static __device__ float g_Wk[D2*D2];
static __device__ float g_Wv[D2*D2];
static __device__ float g_wie[D2*NH];
static __device__ float g_wfe[D2*NH];
static __device__ float g_it[BB*NH*SS];
static __device__ float g_ft[BB*NH*SS];
static __device__ float g_cs[BB*NH*SS];
static __device__ float g_mm[BB*NH*SS];
static __device__ float g_Mx[BB*NH*SS];
static __device__ float g_mtmax[BB*NH*32];

// ---------------- helpers ------------------------------------------------------
__device__ __forceinline__ void mma8(float* d, const unsigned* a, const unsigned* b){
    asm volatile("mma.sync.aligned.m16n8k8.row.col.f32.tf32.tf32.f32 "
        "{%0,%1,%2,%3}, {%4,%5,%6,%7}, {%8,%9}, {%0,%1,%2,%3};\n"
        : "+f"(d[0]), "+f"(d[1]), "+f"(d[2]), "+f"(d[3])
        : "r"(a[0]), "r"(a[1]), "r"(a[2]), "r"(a[3]), "r"(b[0]), "r"(b[1]));
}
__device__ __forceinline__ float silu_f(float x){ return x / (1.f + __expf(-x)); }

// ---------------- layernorm over last dim (512), warp per token ---------------
__global__ void ln_kernel(const float* __restrict__ x,
                          const float* __restrict__ w,
                          const float* __restrict__ b) {
    int t = blockIdx.x * 8 + (threadIdx.x >> 5);
    int lane = threadIdx.x & 31;
    const float* xr = x + (size_t)t * D1;
    float v[16]; float s = 0.f;
#pragma unroll
    for (int i = 0; i < 16; i++) { v[i] = xr[lane + 32*i]; s += v[i]; }
#pragma unroll
    for (int o = 16; o; o >>= 1) s += __shfl_xor_sync(0xffffffffu, s, o);
    float mu = s * (1.f / D1);
    float q = 0.f;
#pragma unroll
    for (int i = 0; i < 16; i++) { float d = v[i] - mu; q += d * d; }
#pragma unroll
    for (int o = 16; o; o >>= 1) q += __shfl_xor_sync(0xffffffffu, q, o);
    float rstd = rsqrtf(q * (1.f / D1) + EPSF);
#pragma unroll
    for (int i = 0; i < 16; i++) {
        int c = lane + 32*i;
        g_xn[(size_t)t*D1 + c] = (v[i] - mu) * rstd * w[c] + b[c];
    }
}

// ---------------- TF32 tensor-core GEMM body (raw fp32 bits, HW truncates) ------
// 128x128 tile, BK=16, 256 threads (8 warps 2x4), warp tile 64x32.
template<int ACT>
__device__ __forceinline__ void tgemm_body(
    const float* __restrict__ A, int lda,
    const float* __restrict__ B, int ldb,
    const float* __restrict__ bias,
    const float* __restrict__ res, int ldr,
    float* __restrict__ C, int ldc, int K, int m0, int n0)
{
    __shared__ float As[2][16][136];
    __shared__ float Bs[2][16][136];
    const int tid = threadIdx.x;
    const int arow = tid >> 2, acol = (tid & 3) * 4;
    const int brow = tid >> 5, bcol = (tid & 31) * 4;
    const int lane = tid & 31, warp = tid >> 5;
    const int grp = lane >> 2, qid = lane & 3;
    const int wm = (warp & 1) * 64, wn = (warp >> 1) * 32;

    const float* Ap0 = A + (size_t)(m0 + arow) * lda + acol;
    const float* Ap1 = A + (size_t)(m0 + arow + 64) * lda + acol;
    const float* Bp0 = B + (size_t)brow * ldb + n0 + bcol;
    const float* Bp1 = B + (size_t)(brow + 8) * ldb + n0 + bcol;

    float acc[4][4][4] = {};
    const int nkt = K >> 4;

    {
        float4 a0 = *(const float4*)Ap0;
        float4 a1 = *(const float4*)Ap1;
        As[0][acol+0][arow] = a0.x; As[0][acol+1][arow] = a0.y;
        As[0][acol+2][arow] = a0.z; As[0][acol+3][arow] = a0.w;
        As[0][acol+0][arow+64] = a1.x; As[0][acol+1][arow+64] = a1.y;
        As[0][acol+2][arow+64] = a1.z; As[0][acol+3][arow+64] = a1.w;
        *(float4*)&Bs[0][brow][bcol]   = *(const float4*)Bp0;
        *(float4*)&Bs[0][brow+8][bcol] = *(const float4*)Bp1;
    }

    int cur = 0;
    for (int kt = 0; kt < nkt; kt++) {
        float4 na0, na1, nb0, nb1;
        if (kt + 1 < nkt) {
            na0 = *(const float4*)(Ap0 + (kt + 1) * 16);
            na1 = *(const float4*)(Ap1 + (kt + 1) * 16);
            nb0 = *(const float4*)(Bp0 + (size_t)(kt + 1) * 16 * ldb);
            nb1 = *(const float4*)(Bp1 + (size_t)(kt + 1) * 16 * ldb);
        }
        __syncthreads();
#pragma unroll
        for (int kk = 0; kk < 16; kk += 8) {
            unsigned aF[4][4], bF[4][2];
#pragma unroll
            for (int mi = 0; mi < 4; mi++) {
                int m = wm + mi * 16 + grp;
                aF[mi][0] = __float_as_uint(As[cur][kk+qid][m]);
                aF[mi][1] = __float_as_uint(As[cur][kk+qid][m+8]);
                aF[mi][2] = __float_as_uint(As[cur][kk+qid+4][m]);
                aF[mi][3] = __float_as_uint(As[cur][kk+qid+4][m+8]);
            }
#pragma unroll
            for (int ni = 0; ni < 4; ni++) {
                int n = wn + ni * 8 + grp;
                bF[ni][0] = __float_as_uint(Bs[cur][kk+qid][n]);
                bF[ni][1] = __float_as_uint(Bs[cur][kk+qid+4][n]);
            }
#pragma unroll
            for (int mi = 0; mi < 4; mi++)
#pragma unroll
                for (int ni = 0; ni < 4; ni++)
                    mma8(acc[mi][ni], aF[mi], bF[ni]);
        }
        if (kt + 1 < nkt) {
            int nxt = cur ^ 1;
            As[nxt][acol+0][arow] = na0.x; As[nxt][acol+1][arow] = na0.y;
            As[nxt][acol+2][arow] = na0.z; As[nxt][acol+3][arow] = na0.w;
            As[nxt][acol+0][arow+64] = na1.x; As[nxt][acol+1][arow+64] = na1.y;
            As[nxt][acol+2][arow+64] = na1.z; As[nxt][acol+3][arow+64] = na1.w;
            *(float4*)&Bs[nxt][brow][bcol]   = nb0;
            *(float4*)&Bs[nxt][brow+8][bcol] = nb1;
            cur = nxt;
        }
    }

#pragma unroll
    for (int mi = 0; mi < 4; mi++) {
        int r0 = m0 + wm + mi * 16 + grp;
#pragma unroll
        for (int ni = 0; ni < 4; ni++) {
            int c = n0 + wn + ni * 8 + qid * 2;
            float b0 = 0.f, b1 = 0.f;
            if (bias) { b0 = bias[c]; b1 = bias[c+1]; }
            float v0 = acc[mi][ni][0] + b0, v1 = acc[mi][ni][1] + b1;
            float v2 = acc[mi][ni][2] + b0, v3 = acc[mi][ni][3] + b1;
            if (ACT == 1) { v0 = silu_f(v0); v1 = silu_f(v1); v2 = silu_f(v2); v3 = silu_f(v3); }
            if (ACT == 2) {
                v0 += res[(size_t)r0*ldr + c];     v1 += res[(size_t)r0*ldr + c + 1];
                v2 += res[(size_t)(r0+8)*ldr + c]; v3 += res[(size_t)(r0+8)*ldr + c + 1];
            }
            *(float2*)(C + (size_t)r0*ldc + c)     = make_float2(v0, v1);
            *(float2*)(C + (size_t)(r0+8)*ldc + c) = make_float2(v2, v3);
        }
    }
}

template<int ACT>
__global__ void __launch_bounds__(256) tgemm(
    const float* __restrict__ A, int lda,
    const float* __restrict__ B, int ldb,
    const float* __restrict__ bias,
    const float* __restrict__ res, int ldr,
    float* __restrict__ C, int ldc, int K)
{
    tgemm_body<ACT>(A, lda, B, ldb, bias, res, ldr, C, ldc, K,
                    blockIdx.y * 128, blockIdx.x * 128);
}

// ---------------- fold block-diagonal weights into dense projections -----------
// Weff[g*256+i][n] = sum_o bw[g][i][o] * W[g*256+o][n]
__global__ void __launch_bounds__(256) foldw(
    const float* __restrict__ bq, const float* __restrict__ bk, const float* __restrict__ bv,
    const float* __restrict__ wq, const float* __restrict__ wk, const float* __restrict__ wv)
{
    int z = blockIdx.z;
    int mat = z >> 2, g = z & 3;
    const float* A = (mat == 0 ? bq : mat == 1 ? bk : bv) + (size_t)g*BLKG*BLKG;
    const float* B = (mat == 0 ? wq : mat == 1 ? wk : wv) + (size_t)g*BLKG*D2;
    float* C = (mat == 0 ? g_Wq : mat == 1 ? g_Wk : g_Wv) + (size_t)g*BLKG*D2;
    tgemm_body<0>(A, BLKG, B, D2, nullptr, nullptr, 0, C, D2, BLKG,
                  blockIdx.y * 128, blockIdx.x * 128);
}

// ---------------- fold gates weights: wi_eff = Bq_bd @ wi, wf_eff = Bk_bd @ wf --
__global__ void foldv(const float* __restrict__ bq, const float* __restrict__ bk,
                      const float* __restrict__ wi, const float* __restrict__ wf) {
    int idx = blockIdx.x * 256 + threadIdx.x;   // 8192
    int r = idx >> 3, h = idx & 7;
    int g = r >> 8, rl = r & 255;
    const float* aq = bq + ((size_t)g*BLKG + rl)*BLKG;
    const float* ak = bk + ((size_t)g*BLKG + rl)*BLKG;
    float si = 0.f, sf = 0.f;
    for (int o = 0; o < BLKG; o++) {
        si = fmaf(aq[o], wi[(g*BLKG + o)*NH + h], si);
        sf = fmaf(ak[o], wf[(g*BLKG + o)*NH + h], sf);
    }
    g_wie[r*NH + h] = si;
    g_wfe[r*NH + h] = sf;
}

// ---------------- conv_w [O,I,K] -> g_wc [K][I][O] ------------------------------
__global__ void conv_tr(const float* __restrict__ cw) {
    int idx = blockIdx.x * 256 + threadIdx.x;
    if (idx >= KSZ * D2 * D2) return;
    int o   = idx >> 12;
    int rem = idx & 4095;
    int i   = rem >> 2;
    int kk  = rem & 3;
    g_wc[((size_t)kk * D2 + i) * D2 + o] = cw[idx];
}

// ---------------- causal conv1d as one K=4096 TF32 GEMM + bias + silu ----------
__global__ void __launch_bounds__(256) tconv(const float* __restrict__ cb)
{
    __shared__ float As[2][16][136];
    __shared__ float Bs[2][16][136];
    const int tid = threadIdx.x;
    const int m0 = blockIdx.y * 128, n0 = blockIdx.x * 128;
    const int arow = tid >> 2, acol = (tid & 3) * 4;
    const int brow = tid >> 5, bcol = (tid & 31) * 4;
    const int lane = tid & 31, warp = tid >> 5;
    const int grp = lane >> 2, qid = lane & 3;
    const int wm = (warp & 1) * 64, wn = (warp >> 1) * 32;
    const int sl0 = (m0 + arow) & (SS - 1);

    float acc[4][4][4] = {};
    const int nkt = (KSZ * D2) >> 4;
    float4 zz = make_float4(0.f, 0.f, 0.f, 0.f);

#define CONV_LOAD(KT, A0, A1, B0, B1)                                               \
    {                                                                               \
        int kc  = (KT) >> 6;                                                        \
        int kin = ((KT) & 63) * 16;                                                 \
        bool ok0 = (sl0 + kc) >= 3;                                                 \
        const float* ar0 = g_a + (size_t)(m0 + arow + kc - 3) * D2 + kin + acol;    \
        const float* ar1 = g_a + (size_t)(m0 + arow + 64 + kc - 3) * D2 + kin + acol;\
        A0 = ok0 ? *(const float4*)ar0 : zz;                                        \
        A1 = *(const float4*)ar1;                                                   \
        const float* br = g_wc + (size_t)((kc << 10) + kin + brow) * D2 + n0 + bcol;\
        B0 = *(const float4*)br;                                                    \
        B1 = *(const float4*)(br + 8 * D2);                                         \
    }

#define SMEM_STORE(BUF, A0, A1, B0, B1)                                             \
    {                                                                               \
        As[BUF][acol+0][arow] = A0.x; As[BUF][acol+1][arow] = A0.y;                 \
        As[BUF][acol+2][arow] = A0.z; As[BUF][acol+3][arow] = A0.w;                 \
        As[BUF][acol+0][arow+64] = A1.x; As[BUF][acol+1][arow+64] = A1.y;           \
        As[BUF][acol+2][arow+64] = A1.z; As[BUF][acol+3][arow+64] = A1.w;           \
        *(float4*)&Bs[BUF][brow][bcol]   = B0;                                      \
        *(float4*)&Bs[BUF][brow+8][bcol] = B1;                                      \
    }

    {
        float4 a0, a1, b0, b1;
        CONV_LOAD(0, a0, a1, b0, b1);
        SMEM_STORE(0, a0, a1, b0, b1);
    }
    int cur = 0;
    for (int kt = 0; kt < nkt; kt++) {
        float4 na0, na1, nb0, nb1;
        if (kt + 1 < nkt) CONV_LOAD(kt + 1, na0, na1, nb0, nb1);
        __syncthreads();
#pragma unroll
        for (int kk = 0; kk < 16; kk += 8) {
            unsigned aF[4][4], bF[4][2];
#pragma unroll
            for (int mi = 0; mi < 4; mi++) {
                int m = wm + mi * 16 + grp;
                aF[mi][0] = __float_as_uint(As[cur][kk+qid][m]);
                aF[mi][1] = __float_as_uint(As[cur][kk+qid][m+8]);
                aF[mi][2] = __float_as_uint(As[cur][kk+qid+4][m]);
                aF[mi][3] = __float_as_uint(As[cur][kk+qid+4][m+8]);
            }
#pragma unroll
            for (int ni = 0; ni < 4; ni++) {
                int n = wn + ni * 8 + grp;
                bF[ni][0] = __float_as_uint(Bs[cur][kk+qid][n]);
                bF[ni][1] = __float_as_uint(Bs[cur][kk+qid+4][n]);
            }
#pragma unroll
            for (int mi = 0; mi < 4; mi++)
#pragma unroll
                for (int ni = 0; ni < 4; ni++)
                    mma8(acc[mi][ni], aF[mi], bF[ni]);
        }
        if (kt + 1 < nkt) {
            int nxt = cur ^ 1;
            SMEM_STORE(nxt, na0, na1, nb0, nb1);
            cur = nxt;
        }
    }

#pragma unroll
    for (int mi = 0; mi < 4; mi++) {
        int r0 = m0 + wm + mi * 16 + grp;
#pragma unroll
        for (int ni = 0; ni < 4; ni++) {
            int c = n0 + wn + ni * 8 + qid * 2;
            float b0 = cb[c], b1 = cb[c+1];
            float v0 = silu_f(acc[mi][ni][0] + b0), v1 = silu_f(acc[mi][ni][1] + b1);
            float v2 = silu_f(acc[mi][ni][2] + b0), v3 = silu_f(acc[mi][ni][3] + b1);
            *(float2*)(g_qk + (size_t)r0*D2 + c)     = make_float2(v0, v1);
            *(float2*)(g_qk + (size_t)(r0+8)*D2 + c) = make_float2(v2, v3);
        }
    }
#undef CONV_LOAD
#undef SMEM_STORE
}

// ---------------- gate pre-activations from qk with folded weights -------------
__global__ void gates_kernel(const float* __restrict__ wib, const float* __restrict__ wfb) {
    int idx = blockIdx.x * blockDim.x + threadIdx.x;   // TOK*NH threads
    int t = idx >> 3, h = idx & 7;
    float si = 0.f, sf = 0.f;
    const float* xr = g_qk + (size_t)t * D2;
    for (int i = 0; i < D2; i++) {
        float xv = xr[i];
        si = fmaf(xv, g_wie[i*NH + h], si);
        sf = fmaf(xv, g_wfe[i*NH + h], sf);
    }
    int b = t >> 11, s = t & (SS - 1);
    g_it[((size_t)b*NH + h)*SS + s] = si + wib[h];
    g_ft[((size_t)b*NH + h)*SS + s] = sf + wfb[h];
}

// ---------------- per-(b,h) scans ----------------------------------------------
__global__ void scan_kernel() {
    int bh = blockIdx.x;
    int tid = threadIdx.x;
    int lane = tid & 31, w = tid >> 5;
    __shared__ float ws[8], wm[8];
    float carry_s = 0.f, carry_m = -1e30f;
    for (int c0 = 0; c0 < SS; c0 += 256) {
        int j = c0 + tid;
        float f = g_ft[(size_t)bh*SS + j];
        float ls = fminf(f, 0.f) - log1pf(expf(-fabsf(f)));
        float v = ls;
#pragma unroll
        for (int o = 1; o < 32; o <<= 1) {
            float u = __shfl_up_sync(0xffffffffu, v, o);
            if (lane >= o) v += u;
        }
        if (lane == 31) ws[w] = v;
        __syncthreads();
        if (tid == 0) { float run = 0.f; for (int i = 0; i < 8; i++) { run += ws[i]; ws[i] = run; } }
        __syncthreads();
        float cs = v + (w ? ws[w-1] : 0.f) + carry_s;
        g_cs[(size_t)bh*SS + j] = cs;
        float m = g_it[(size_t)bh*SS + j] - cs;
        g_mm[(size_t)bh*SS + j] = m;
        float mv = m;
#pragma unroll
        for (int o = 1; o < 32; o <<= 1) {
            float u = __shfl_up_sync(0xffffffffu, mv, o);
            if (lane >= o) mv = fmaxf(mv, u);
        }
        if (lane == 31) wm[w] = mv;
        __syncthreads();
        if (tid == 0) { float run = -1e30f; for (int i = 0; i < 8; i++) { run = fmaxf(run, wm[i]); wm[i] = run; } }
        __syncthreads();
        float Mpref = fmaxf(mv, w ? wm[w-1] : -1e30f);
        g_Mx[(size_t)bh*SS + j] = fmaxf(Mpref, carry_m);
        carry_s += ws[7];
        carry_m = fmaxf(carry_m, wm[7]);
        __syncthreads();
    }
}

// ---------------- per-64-tile maxima of m ---------------------------------------
__global__ void tilemax_kernel() {
    int bh = blockIdx.x;
    int t  = threadIdx.x;
    float mx = -1e30f;
    const float* mr = g_mm + (size_t)bh*SS + t*64;
    for (int i = 0; i < 64; i++) mx = fmaxf(mx, mr[i]);
    g_mtmax[bh*32 + t] = mx;
}

// ---------------- tensor-core mLSTM attention -----------------------------------
#define PADQ 132
#define PADK 132
#define PADV 136
#define PADP 72
#define ATTN_SMEM_FLOATS (64*PADQ + 64*PADV + 64*PADP + 64 + 128 + 64)

__global__ void __launch_bounds__(256) attn_tc() {
    extern __shared__ float sm[];
    float* Qs  = sm;                 // [64][132]
    float* KVs = Qs + 64*PADQ;       // K stride 132 / V stride 136 (union)
    float* Ps  = KVs + 64*PADV;      // [64][72]
    float* mms = Ps + 64*PADP;       // [64]
    float* red = mms + 64;           // [64][2]
    float* inv = red + 128;          // [64]

    int bh = blockIdx.y, b = bh >> 3, h = bh & 7;
    int qt = gridDim.x - 1 - blockIdx.x;     // big tiles first
    int row0 = qt * 64;
    int tid = threadIdx.x, lane = tid & 31, warp = tid >> 5;
    int grp = lane >> 2, qid = lane & 3;
    int wm = (warp >> 1) * 16;       // row tile (S and H)
    int wn = (warp & 1) * 32;        // S col tile
    int wn2 = (warp & 1) * 64;       // H col tile
    int tok0 = b * SS + row0;

    for (int i = tid; i < 64*32; i += 256) {
        int r = i >> 5, d4 = (i & 31) * 4;
        *(float4*)&Qs[r*PADQ + d4] = *(const float4*)&g_qh[(size_t)(tok0+r)*D2 + h*HD + d4];
    }
    float Mi0 = g_Mx[(size_t)bh*SS + row0 + wm + grp];
    float Mi1 = g_Mx[(size_t)bh*SS + row0 + wm + grp + 8];
    float Mtop = g_Mx[(size_t)bh*SS + row0];

    float hacc[8][4] = {};
    float rs0 = 0.f, rs1 = 0.f;
    const float inv_tau = 0.03125f;

    for (int jt = 0; jt <= qt; jt++) {
        if (jt < qt && g_mtmax[bh*32 + jt] < Mtop - 35.f) continue;
        int jr0 = jt * 64;
        __syncthreads();
        for (int i = tid; i < 64*32; i += 256) {
            int r = i >> 5, d4 = (i & 31) * 4;
            *(float4*)&KVs[r*PADK + d4] = *(const float4*)&g_kh[(size_t)(b*SS+jr0+r)*D2 + h*HD + d4];
        }
        if (tid < 64) mms[tid] = g_mm[(size_t)bh*SS + jr0 + tid];
        __syncthreads();

        // S = Q @ K^T
        float sacc[4][4] = {};
#pragma unroll
        for (int d0 = 0; d0 < HD; d0 += 8) {
            unsigned aF[4];
            aF[0] = __float_as_uint(Qs[(wm+grp)*PADQ + d0 + qid]);
            aF[1] = __float_as_uint(Qs[(wm+grp+8)*PADQ + d0 + qid]);
            aF[2] = __float_as_uint(Qs[(wm+grp)*PADQ + d0 + qid + 4]);
            aF[3] = __float_as_uint(Qs[(wm+grp+8)*PADQ + d0 + qid + 4]);
#pragma unroll
            for (int ni = 0; ni < 4; ni++) {
                int jn = wn + ni*8 + grp;
                unsigned bF[2];
                bF[0] = __float_as_uint(KVs[jn*PADK + d0 + qid]);
                bF[1] = __float_as_uint(KVs[jn*PADK + d0 + qid + 4]);
                mma8(sacc[ni], aF, bF);
            }
        }
        // decay + causal mask -> P (smem), rowsum
#pragma unroll
        for (int ni = 0; ni < 4; ni++) {
            int c0 = wn + ni*8 + 2*qid;
            int gj0 = jr0 + c0, gj1 = gj0 + 1;
            int gi0 = row0 + wm + grp, gi1 = gi0 + 8;
            float e0 = mms[c0], e1 = mms[c0+1];
            float p00 = (gj0 <= gi0) ? sacc[ni][0] * inv_tau * __expf(e0 - Mi0) : 0.f;
            float p01 = (gj1 <= gi0) ? sacc[ni][1] * inv_tau * __expf(e1 - Mi0) : 0.f;
            float p10 = (gj0 <= gi1) ? sacc[ni][2] * inv_tau * __expf(e0 - Mi1) : 0.f;
            float p11 = (gj1 <= gi1) ? sacc[ni][3] * inv_tau * __expf(e1 - Mi1) : 0.f;
            rs0 += p00 + p01; rs1 += p10 + p11;
            *(float2*)&Ps[(wm+grp)*PADP + c0]   = make_float2(p00, p01);
            *(float2*)&Ps[(wm+grp+8)*PADP + c0] = make_float2(p10, p11);
        }
        __syncthreads();
        // load V (stride 136)
        for (int i = tid; i < 64*32; i += 256) {
            int r = i >> 5, d4 = (i & 31) * 4;
            *(float4*)&KVs[r*PADV + d4] = *(const float4*)&g_vh[(size_t)(b*SS+jr0+r)*D2 + h*HD + d4];
        }
        __syncthreads();
        // H += P @ V
#pragma unroll
        for (int k0 = 0; k0 < 64; k0 += 8) {
            unsigned aF[4];
            aF[0] = __float_as_uint(Ps[(wm+grp)*PADP + k0 + qid]);
            aF[1] = __float_as_uint(Ps[(wm+grp+8)*PADP + k0 + qid]);
            aF[2] = __float_as_uint(Ps[(wm+grp)*PADP + k0 + qid + 4]);
            aF[3] = __float_as_uint(Ps[(wm+grp+8)*PADP + k0 + qid + 4]);
#pragma unroll
            for (int ni = 0; ni < 8; ni++) {
                int dn = wn2 + ni*8 + grp;
                unsigned bF[2];
                bF[0] = __float_as_uint(KVs[(k0+qid)*PADV + dn]);
                bF[1] = __float_as_uint(KVs[(k0+qid+4)*PADV + dn]);
                mma8(hacc[ni], aF, bF);
            }
        }
    }

    // rowsum reduce (within quad, then across n-warps via smem)
    rs0 += __shfl_xor_sync(0xffffffffu, rs0, 1);
    rs0 += __shfl_xor_sync(0xffffffffu, rs0, 2);
    rs1 += __shfl_xor_sync(0xffffffffu, rs1, 1);
    rs1 += __shfl_xor_sync(0xffffffffu, rs1, 2);
    if (qid == 0) {
        red[(wm+grp)*2 + (warp & 1)]   = rs0;
        red[(wm+grp+8)*2 + (warp & 1)] = rs1;
    }
    __syncthreads();
    if (tid < 64) {
        float s2 = red[tid*2] + red[tid*2 + 1];
        int gi = row0 + tid;
        float floorv = __expf(-g_cs[(size_t)bh*SS + gi] - g_Mx[(size_t)bh*SS + gi]);
        inv[tid] = 1.f / (fmaxf(fabsf(s2), floorv) + 1e-8f);
    }
    __syncthreads();
    float iv0 = inv[wm + grp], iv1 = inv[wm + grp + 8];
#pragma unroll
    for (int ni = 0; ni < 8; ni++) {
        int dn = wn2 + ni*8 + 2*qid;
        size_t o0 = (size_t)(tok0 + wm + grp)*D2 + h*HD + dn;
        size_t o1 = (size_t)(tok0 + wm + grp + 8)*D2 + h*HD + dn;
        *(float2*)&g_Ho[o0] = make_float2(hacc[ni][0]*iv0, hacc[ni][1]*iv0);
        *(float2*)&g_Ho[o1] = make_float2(hacc[ni][2]*iv1, hacc[ni][3]*iv1);
    }
}

// ---------------- GroupNorm(heads) + skip*qk, then *bgate ---------------------
__global__ void gn_kernel(const float* __restrict__ gnw, const float* __restrict__ gnb,
                          const float* __restrict__ skip) {
    int g = blockIdx.x * 8 + (threadIdx.x >> 5);
    int lane = threadIdx.x & 31;
    int t = g >> 3, h = g & 7;
    const float* Hr = g_Ho + (size_t)t * D2 + h * HD;
    float4 v4 = *(const float4*)(Hr + lane * 4);
    float vv[4] = {v4.x, v4.y, v4.z, v4.w};
    float s = vv[0] + vv[1] + vv[2] + vv[3];
#pragma unroll
    for (int o = 16; o; o >>= 1) s += __shfl_xor_sync(0xffffffffu, s, o);
    float mu = s * (1.f / HD);
    float q = 0.f;
#pragma unroll
    for (int j = 0; j < 4; j++) { float d = vv[j] - mu; q += d * d; }
#pragma unroll
    for (int o = 16; o; o >>= 1) q += __shfl_xor_sync(0xffffffffu, q, o);
    float rstd = rsqrtf(q * (1.f / HD) + EPSF);
#pragma unroll
    for (int j = 0; j < 4; j++) {
        int c = h * HD + lane * 4 + j;
        float val = (vv[j] - mu) * rstd * gnw[c] + gnb[c];
        val += skip[c] * g_qk[(size_t)t * D2 + c];
        val *= g_bg[(size_t)t * D2 + c];
        g_h2[(size_t)t * D2 + c] = val;
    }
}

// ------------------------------- launcher --------------------------------------
extern "C" void kernel_launch(void* const* d_in, const int* in_sizes, int n_in,
                              void* d_out, int out_size) {
    (void)in_sizes; (void)n_in; (void)out_size;
    const float* x      = (const float*)d_in[0];
    const float* ln_w   = (const float*)d_in[1];
    const float* ln_b   = (const float*)d_in[2];
    const float* mlp1_w = (const float*)d_in[3];
    const float* mlp1_b = (const float*)d_in[4];
    const float* mlp2_w = (const float*)d_in[5];
    const float* mlp2_b = (const float*)d_in[6];
    const float* conv_w = (const float*)d_in[7];
    const float* conv_b = (const float*)d_in[8];
    const float* bq_w   = (const float*)d_in[9];
    const float* bk_w   = (const float*)d_in[10];
    const float* bv_w   = (const float*)d_in[11];
    const float* wq_w   = (const float*)d_in[12];
    const float* wq_b   = (const float*)d_in[13];
    const float* wk_w   = (const float*)d_in[14];
    const float* wk_b   = (const float*)d_in[15];
    const float* wv_w   = (const float*)d_in[16];
    const float* wv_b   = (const float*)d_in[17];
    const float* wi_w   = (const float*)d_in[18];
    const float* wi_b   = (const float*)d_in[19];
    const float* wf_w   = (const float*)d_in[20];
    const float* wf_b   = (const float*)d_in[21];
    const float* gn_w   = (const float*)d_in[22];
    const float* gn_b   = (const float*)d_in[23];
    const float* skip   = (const float*)d_in[24];
    const float* fin_w  = (const float*)d_in[25];
    const float* fin_b  = (const float*)d_in[26];

    float *xn, *a, *bg, *qk, *qh, *kh, *vh, *h2, *Wq, *Wk, *Wv;
    cudaGetSymbolAddress((void**)&xn, g_xn);
    cudaGetSymbolAddress((void**)&a,  g_a);
    cudaGetSymbolAddress((void**)&bg, g_bg);
    cudaGetSymbolAddress((void**)&qk, g_qk);
    cudaGetSymbolAddress((void**)&qh, g_qh);
    cudaGetSymbolAddress((void**)&kh, g_kh);
    cudaGetSymbolAddress((void**)&vh, g_vh);
    cudaGetSymbolAddress((void**)&h2, g_h2);
    cudaGetSymbolAddress((void**)&Wq, g_Wq);
    cudaGetSymbolAddress((void**)&Wk, g_Wk);
    cudaGetSymbolAddress((void**)&Wv, g_Wv);

    // weight preprocessing (independent of activations)
    conv_tr<<<(KSZ*D2*D2 + 255)/256, 256>>>(conv_w);
    foldw<<<dim3(8, 2, 12), 256>>>(bq_w, bk_w, bv_w, wq_w, wk_w, wv_w);
    foldv<<<32, 256>>>(bq_w, bk_w, wi_w, wf_w);

    ln_kernel<<<TOK/8, 256>>>(x, ln_w, ln_b);

    dim3 gD2(D2/128, TOK/128);          // (8, 32)
    tgemm<0><<<gD2, 256>>>(xn, D1, mlp1_w, D2, mlp1_b, nullptr, 0, a,  D2, D1);
    tgemm<1><<<gD2, 256>>>(xn, D1, mlp2_w, D2, mlp2_b, nullptr, 0, bg, D2, D1);

    // causal conv (K=4096 virtual GEMM) + bias + silu -> qk
    tconv<<<gD2, 256>>>(conv_b);

    // fused (block-diag ∘ dense) projections
    tgemm<0><<<gD2, 256>>>(qk, D2, Wq, D2, wq_b, nullptr, 0, qh, D2, D2);
    tgemm<0><<<gD2, 256>>>(qk, D2, Wk, D2, wk_b, nullptr, 0, kh, D2, D2);
    tgemm<0><<<gD2, 256>>>(a,  D2, Wv, D2, wv_b, nullptr, 0, vh, D2, D2);

    // gates + scans + tile maxima
    gates_kernel<<<TOK*NH/256, 256>>>(wi_b, wf_b);
    scan_kernel<<<BB*NH, 256>>>();
    tilemax_kernel<<<BB*NH, 32>>>();

    // attention (tensor cores)
    const int attn_smem = ATTN_SMEM_FLOATS * 4;
    cudaFuncSetAttribute(attn_tc, cudaFuncAttributeMaxDynamicSharedMemorySize, attn_smem);
    attn_tc<<<dim3(SS/64, BB*NH), 256, attn_smem>>>();

    gn_kernel<<<TOK*NH/8, 256>>>(gn_w, gn_b, skip);

    // final GEMM + residual -> d_out
    dim3 gF(D1/128, TOK/128);
    tgemm<2><<<gF, 256>>>(h2, D2, fin_w, D1, fin_b, x, D1,
                          (float*)d_out, D1, D2);
}